// round 2
// baseline (speedup 1.0000x reference)
#include <cuda_runtime.h>
#include <cstddef>

// Problem constants
#define BATCH 8
#define TSEQ  1024
#define DDIM  384
#define DLANG 768
#define HID   512

// Scratch (allocation-free rule: __device__ globals)
__device__ float g_buf0[BATCH * HID];
__device__ float g_buf1[BATCH * HID];
__device__ float g_f[BATCH * DDIM];

// ---------------------------------------------------------------------------
// GEMV stage: out[b, j] = sum_i in[b, i] * W[i, j] + bias[j]
// W is row-major [K, N]. Grid: (N/32, B). Block: 256 threads = 8 k-slices x 32 j.
// ---------------------------------------------------------------------------
template <int K, int N>
__global__ void gemv_stage(const float* __restrict__ in,
                           const float* __restrict__ W,
                           const float* __restrict__ bias,
                           float* __restrict__ out) {
    const int b = blockIdx.y;
    const int jbase = blockIdx.x * 32;

    __shared__ float sin[K];
    __shared__ float spart[8][32];

    const float* inb = in + b * K;
    for (int i = threadIdx.x; i < K; i += 256) sin[i] = inb[i];
    __syncthreads();

    const int ks = threadIdx.x >> 5;   // 0..7
    const int jj = threadIdx.x & 31;
    const int j = jbase + jj;
    constexpr int KS = K / 8;

    float acc = 0.0f;
    const float* Wp = W + (size_t)(ks * KS) * N + j;
    const float* sp = sin + ks * KS;
#pragma unroll 8
    for (int i = 0; i < KS; ++i) {
        acc += sp[i] * Wp[(size_t)i * N];
    }
    spart[ks][jj] = acc;
    __syncthreads();

    if (threadIdx.x < 32) {
        float s = bias[j];
#pragma unroll
        for (int k = 0; k < 8; ++k) s += spart[k][jj];
        out[b * N + j] = s;
    }
}

// ---------------------------------------------------------------------------
// Residual broadcast add: out[b,t,d] = state[b,t,d] + f[b,d]
// Grid: (T/32, B). Block: 256 threads. Each block: 32 rows of 384 floats
// = 3072 float4 -> 12 float4 per thread (MLP ~12).
// ---------------------------------------------------------------------------
__global__ void residual_add(const float* __restrict__ state,
                             const float* __restrict__ f,
                             float* __restrict__ out) {
    const int b = blockIdx.y;
    const int t0 = blockIdx.x * 32;

    __shared__ float4 fsh[DDIM / 4];  // 96
    if (threadIdx.x < DDIM / 4) {
        fsh[threadIdx.x] = reinterpret_cast<const float4*>(f + b * DDIM)[threadIdx.x];
    }
    __syncthreads();

    const size_t base = ((size_t)b * TSEQ + t0) * DDIM;
    const float4* sp = reinterpret_cast<const float4*>(state + base);
    float4* op = reinterpret_cast<float4*>(out + base);

#pragma unroll
    for (int it = 0; it < 12; ++it) {
        int p = threadIdx.x + it * 256;   // 0..3071
        int dq = p % (DDIM / 4);
        float4 s = sp[p];
        float4 fv = fsh[dq];
        s.x += fv.x; s.y += fv.y; s.z += fv.z; s.w += fv.w;
        op[p] = s;
    }
}

// ---------------------------------------------------------------------------
// Inputs (metadata order):
//  0 state [B,T,D]   1 language [B,DL]
//  2 Wq 3 bq 4 Wk 5 bk 6 Wv 7 bv
//  8 Wq2 9 bq2 10 Wk2 11 bk2 12 Wv2 13 bv2
// 14 Wo 15 bo 16 Wout 17 bout
// Output: float32 [B,T,D]
//
// Math note: language is broadcast along T, so k/v are identical for all key
// positions; softmax over a constant row is uniform 1/T, and ctx == v exactly.
// The whole Q path and the T x T attention cancel analytically. What remains:
//   f[b] = (((language[b] Wv + bv) Wv2 + bv2) Wo + bo) Wout + bout
//   out[b,t,:] = state[b,t,:] + f[b,:]
// ---------------------------------------------------------------------------
extern "C" void kernel_launch(void* const* d_in, const int* in_sizes, int n_in,
                              void* d_out, int out_size) {
    (void)in_sizes; (void)n_in; (void)out_size;

    const float* state    = (const float*)d_in[0];
    const float* language = (const float*)d_in[1];
    const float* Wv   = (const float*)d_in[6];
    const float* bv   = (const float*)d_in[7];
    const float* Wv2  = (const float*)d_in[12];
    const float* bv2  = (const float*)d_in[13];
    const float* Wo   = (const float*)d_in[14];
    const float* bo   = (const float*)d_in[15];
    const float* Wout = (const float*)d_in[16];
    const float* bout = (const float*)d_in[17];
    float* out = (float*)d_out;

    static float* buf0 = nullptr;
    static float* buf1 = nullptr;
    static float* fbuf = nullptr;
    if (!buf0) {
        cudaGetSymbolAddress((void**)&buf0, g_buf0);
        cudaGetSymbolAddress((void**)&buf1, g_buf1);
        cudaGetSymbolAddress((void**)&fbuf, g_f);
    }

    // GEMV chain (Q path and full attention cancel analytically; see note)
    gemv_stage<DLANG, HID><<<dim3(HID / 32, BATCH), 256>>>(language, Wv,   bv,   buf0);
    gemv_stage<HID,   HID><<<dim3(HID / 32, BATCH), 256>>>(buf0,     Wv2,  bv2,  buf1);
    gemv_stage<HID,   HID><<<dim3(HID / 32, BATCH), 256>>>(buf1,     Wo,   bo,   buf0);
    gemv_stage<HID,  DDIM><<<dim3(DDIM / 32, BATCH), 256>>>(buf0,    Wout, bout, fbuf);

    // Broadcast residual add
    residual_add<<<dim3(TSEQ / 32, BATCH), 256>>>(state, fbuf, out);
}